// round 14
// baseline (speedup 1.0000x reference)
#include <cuda_runtime.h>
#include <cuda_fp16.h>
#include <cstdint>

#define BATCH 4
#define N 4097
#define D 128
#define H 8
#define DH 16
#define ROWS (BATCH * N)
#define KTILE 128
#define QTILE 128
#define NKT 33
#define NQT 33
#define RS 24    // half-stride for 16-col tiles (48B, ldsm conflict-free)
#define XRS 136  // 128-col tile row stride (halfs)

#define QKV_SMEM   ((64 * XRS + 128 * XRS) * 2)     // 52224 B
#define PROJ_SMEM  (4 * 128 * XRS * 2)              // 139264 B
#define TILE_HALFS (KTILE * RS)

// ---------------- scratch (allocation-free rule) ----------------
// Flat layouts [row][128], column = head*16 + d. Q pre-scaled by d^-.5*log2e.
__device__ __align__(16) __half g_Q[ROWS * D];
__device__ __align__(16) __half g_K[ROWS * D];
__device__ __align__(16) __half g_V[ROWS * D];
__device__ __align__(16) __half g_Ohi[ROWS * D];
__device__ __align__(16) __half g_Olo[ROWS * D];
__device__ __align__(16) __half g_xh[ROWS * D];     // x in fp16
__device__ __align__(16) __half g_wqh[D * 384];     // W_qkv in fp16
__device__ __align__(16) __half g_pwh[D * D];       // W_out hi
__device__ __align__(16) __half g_pwl[D * D];       // W_out lo

__device__ __forceinline__ uint32_t smem_u32(const void* p) {
    uint32_t a;
    asm("{ .reg .u64 t; cvta.to.shared.u64 t, %1; cvt.u32.u64 %0, t; }" : "=r"(a) : "l"(p));
    return a;
}
__device__ __forceinline__ void ldsm_x4(uint32_t a, uint32_t& r0, uint32_t& r1,
                                        uint32_t& r2, uint32_t& r3) {
    asm volatile("ldmatrix.sync.aligned.m8n8.x4.shared.b16 {%0,%1,%2,%3}, [%4];"
                 : "=r"(r0), "=r"(r1), "=r"(r2), "=r"(r3) : "r"(a));
}
__device__ __forceinline__ void ldsm_x4_t(uint32_t a, uint32_t& r0, uint32_t& r1,
                                          uint32_t& r2, uint32_t& r3) {
    asm volatile("ldmatrix.sync.aligned.m8n8.x4.trans.shared.b16 {%0,%1,%2,%3}, [%4];"
                 : "=r"(r0), "=r"(r1), "=r"(r2), "=r"(r3) : "r"(a));
}
__device__ __forceinline__ void mma16816(float* d, const uint32_t* a,
                                         uint32_t b0, uint32_t b1, const float* c) {
    asm volatile("mma.sync.aligned.m16n8k16.row.col.f32.f16.f16.f32 "
        "{%0,%1,%2,%3}, {%4,%5,%6,%7}, {%8,%9}, {%10,%11,%12,%13};"
        : "=f"(d[0]), "=f"(d[1]), "=f"(d[2]), "=f"(d[3])
        : "r"(a[0]), "r"(a[1]), "r"(a[2]), "r"(a[3]), "r"(b0), "r"(b1),
          "f"(c[0]), "f"(c[1]), "f"(c[2]), "f"(c[3]));
}
__device__ __forceinline__ uint4 cvt4(float4 a, float4 b) {
    uint4 u;
    __half2 h0 = __floats2half2_rn(a.x, a.y), h1 = __floats2half2_rn(a.z, a.w);
    __half2 h2 = __floats2half2_rn(b.x, b.y), h3 = __floats2half2_rn(b.z, b.w);
    u.x = *(uint32_t*)&h0; u.y = *(uint32_t*)&h1;
    u.z = *(uint32_t*)&h2; u.w = *(uint32_t*)&h3;
    return u;
}
__device__ __forceinline__ void cp16(uint32_t dst, const void* src) {
    asm volatile("cp.async.cg.shared.global [%0], [%1], 16;"
                 :: "r"(dst), "l"(src));
}

// ---------------------------------------------------------------------------
// Kernel 0: one-shot conversions (x->fp16, W_qkv->fp16, W_out->hi/lo fp16)
// ---------------------------------------------------------------------------
__global__ void conv_kernel(const float* __restrict__ x,
                            const float* __restrict__ Wqkv,
                            const float* __restrict__ Wout) {
    const int tid = blockIdx.x * blockDim.x + threadIdx.x;
    const int nt = gridDim.x * blockDim.x;

    for (int i = tid; i < (ROWS * D) / 8; i += nt) {
        const float4* s = (const float4*)x + 2 * i;
        ((uint4*)g_xh)[i] = cvt4(s[0], s[1]);
    }
    for (int i = tid; i < (D * 384) / 8; i += nt) {
        const float4* s = (const float4*)Wqkv + 2 * i;
        ((uint4*)g_wqh)[i] = cvt4(s[0], s[1]);
    }
    for (int i = tid; i < (D * D) / 8; i += nt) {
        const float4* s = (const float4*)Wout + 2 * i;
        float4 f0 = s[0], f1 = s[1];
        float wv[8] = {f0.x, f0.y, f0.z, f0.w, f1.x, f1.y, f1.z, f1.w};
        __half hh[8], hl[8];
#pragma unroll
        for (int k = 0; k < 8; k++) {
            hh[k] = __float2half_rn(wv[k]);
            hl[k] = __float2half_rn(wv[k] - __half2float(hh[k]));
        }
        ((uint4*)g_pwh)[i] = *(uint4*)hh;
        ((uint4*)g_pwl)[i] = *(uint4*)hl;
    }
}

// ---------------------------------------------------------------------------
// Kernel 1: QKV GEMM (unchanged from R12 best).
// ---------------------------------------------------------------------------
__global__ void __launch_bounds__(128) qkv_mma_kernel(const float* __restrict__ bias) {
    extern __shared__ __align__(16) char qsm[];
    __half* xs = (__half*)qsm;
    __half* ws = (__half*)(qsm + 64 * XRS * 2);
    const int t = threadIdx.x, w = t >> 5, lane = t & 31;
    const int row0 = blockIdx.x * 64;
    const int cg = blockIdx.y * 128;

    const int grp = lane >> 3, r8 = lane & 7;
    const uint32_t fragA = (uint32_t)((((grp & 1) * 8 + r8) * XRS + (grp >> 1) * 8) * 2);
    const uint32_t xsb = smem_u32(xs), wsb = smem_u32(ws);

#pragma unroll
    for (int c = t; c < 1024; c += 128) {
        int r = c >> 4, s = c & 15;
        int row = row0 + r; if (row >= ROWS) row = ROWS - 1;
        cp16(xsb + (uint32_t)((r * XRS + s * 8) * 2), g_xh + (size_t)row * D + s * 8);
    }
#pragma unroll
    for (int c = t; c < 2048; c += 128) {
        int r = c >> 4, s = c & 15;
        cp16(wsb + (uint32_t)((r * XRS + s * 8) * 2), g_wqh + (size_t)r * 384 + cg + s * 8);
    }
    asm volatile("cp.async.commit_group;");
    asm volatile("cp.async.wait_group 0;" ::: "memory");
    __syncthreads();

    float acc[16][4];
#pragma unroll
    for (int i = 0; i < 16; i++)
#pragma unroll
        for (int j = 0; j < 4; j++) acc[i][j] = 0.f;

#pragma unroll
    for (int ks = 0; ks < 8; ks++) {
        uint32_t af[4];
        ldsm_x4(xsb + (uint32_t)((w * 16 * XRS + ks * 16) * 2) + fragA,
                af[0], af[1], af[2], af[3]);
#pragma unroll
        for (int g = 0; g < 8; g++) {
            uint32_t b0, b1, b2, b3;
            ldsm_x4_t(wsb + (uint32_t)((ks * 16 * XRS + g * 16) * 2) + fragA,
                      b0, b1, b2, b3);
            mma16816(acc[2 * g],     af, b0, b1, acc[2 * g]);
            mma16816(acc[2 * g + 1], af, b2, b3, acc[2 * g + 1]);
        }
    }

    const float QSCALE = (float)(0.08838834764831845 * 1.4426950408889634);
    __half* dst = (blockIdx.y == 0) ? g_Q : (blockIdx.y == 1 ? g_K : g_V);
    const float sc = (blockIdx.y == 0) ? QSCALE : 1.0f;
    const int r0 = row0 + w * 16 + (lane >> 2);
#pragma unroll
    for (int nt = 0; nt < 16; nt++) {
        const int col = nt * 8 + 2 * (lane & 3);
        const float b0v = bias[cg + col], b1v = bias[cg + col + 1];
#pragma unroll
        for (int rr = 0; rr < 2; rr++) {
            int row = r0 + rr * 8;
            if (row < ROWS) {
                __half2 hv = __floats2half2_rn((acc[nt][2 * rr]     + b0v) * sc,
                                               (acc[nt][2 * rr + 1] + b1v) * sc);
                *(__half2*)(dst + row * D + col) = hv;
            }
        }
    }
}

// ---------------------------------------------------------------------------
// Kernel 2: FA2-style fp16 flash attention. QTILE=128, 8 warps, 3 CTAs/SM.
// 4-deep K/V ring; barrier every 2 tiles; E/O split accumulators (R12 body).
// ---------------------------------------------------------------------------
__global__ void __launch_bounds__(256, 3) attn_kernel() {
    __shared__ __align__(16) __half sQ[QTILE * RS];
    __shared__ __align__(16) __half sK[4][TILE_HALFS];
    __shared__ __align__(16) __half sV[4][TILE_HALFS];

    const int t = threadIdx.x, w = t >> 5, lane = t & 31;
    const int qt = blockIdx.x, hi = blockIdx.y, bi = blockIdx.z;

    const __half* Qb = g_Q + (size_t)(bi * N) * D + hi * DH;
    const __half* Kb = g_K + (size_t)(bi * N) * D + hi * DH;
    const __half* Vb = g_V + (size_t)(bi * N) * D + hi * DH;

    const int srow = t >> 1, sc8 = (t & 1) * 8;
    {
        int qr = qt * QTILE + srow; if (qr >= N) qr = N - 1;
        *(uint4*)(sQ + srow * RS + sc8) = *(const uint4*)(Qb + (size_t)qr * D + sc8);
        // tile 0: direct load
        *(uint4*)(sK[0] + srow * RS + sc8) = *(const uint4*)(Kb + (size_t)srow * D + sc8);
        *(uint4*)(sV[0] + srow * RS + sc8) = *(const uint4*)(Vb + (size_t)srow * D + sc8);
    }
    // prefetch tile 1 (group #1); keys 128..255 all < N
    {
        int key = KTILE + srow;
        cp16(smem_u32(sK[1] + srow * RS + sc8), Kb + (size_t)key * D + sc8);
        cp16(smem_u32(sV[1] + srow * RS + sc8), Vb + (size_t)key * D + sc8);
    }
    asm volatile("cp.async.commit_group;");
    __syncthreads();

    const int grp = lane >> 3, r8 = lane & 7;
    const uint32_t frag_off =
        (uint32_t)((((grp & 1) * 8 + r8) * RS + (grp >> 1) * 8) * 2);

    uint32_t qf[4];
    ldsm_x4(smem_u32(sQ) + (uint32_t)(w * 16 * RS * 2) + frag_off,
            qf[0], qf[1], qf[2], qf[3]);

    uint32_t kbase[4], vbase[4], kdst[4], vdst[4];
#pragma unroll
    for (int b = 0; b < 4; b++) {
        kbase[b] = smem_u32(sK[b]) + frag_off;
        vbase[b] = smem_u32(sV[b]) + frag_off;
        kdst[b]  = smem_u32(sK[b] + srow * RS + sc8);
        vdst[b]  = smem_u32(sV[b] + srow * RS + sc8);
    }
    const uint32_t ONES = 0x3C003C00u;
    const float z4[4] = {0.f, 0.f, 0.f, 0.f};

    float oaccE[2][4] = {{0.f,0.f,0.f,0.f},{0.f,0.f,0.f,0.f}};
    float oaccO[2][4] = {{0.f,0.f,0.f,0.f},{0.f,0.f,0.f,0.f}};
    float laccE[4] = {0.f,0.f,0.f,0.f};
    float laccO[4] = {0.f,0.f,0.f,0.f};

    for (int e = 0; e < NKT; e += 2) {
        // prefetch tiles e+2, e+3 (one group each; empty groups if out of range)
#pragma unroll
        for (int p = 2; p < 4; p++) {
            int kt = e + p;
            if (kt < NKT) {
                int key = kt * KTILE + srow;
                int sz = (key < N) ? 16 : 0;
                int keyc = (key < N) ? key : (N - 1);
                int b = kt & 3;
                asm volatile("cp.async.cg.shared.global [%0], [%1], 16, %2;"
                             :: "r"(kdst[b]), "l"(Kb + (size_t)keyc * D + sc8), "r"(sz));
                asm volatile("cp.async.cg.shared.global [%0], [%1], 16, %2;"
                             :: "r"(vdst[b]), "l"(Vb + (size_t)keyc * D + sc8), "r"(sz));
            }
            asm volatile("cp.async.commit_group;");
        }

#pragma unroll
        for (int sub = 0; sub < 2; sub++) {
            const int kt = e + sub;
            if (kt >= NKT) break;
            if (sub == 0) {
                asm volatile("cp.async.wait_group 3;" ::: "memory");
            } else {
                asm volatile("cp.async.wait_group 2;" ::: "memory");
            }
            const int k0 = kt * KTILE;
            const int b = kt & 3;
            const uint32_t kb = kbase[b], vb = vbase[b];
            const bool tail = (k0 + KTILE > N);

#pragma unroll
            for (int g = 0; g < 8; g++) {
                uint32_t b0, b1, b2, b3;
                ldsm_x4(kb + (uint32_t)(g * 16 * RS * 2), b0, b1, b2, b3);
                float s0[4], s1[4];
                mma16816(s0, qf, b0, b2, z4);
                mma16816(s1, qf, b1, b3, z4);

                uint32_t v0, v1, v2, v3;
                ldsm_x4_t(vb + (uint32_t)(g * 16 * RS * 2), v0, v1, v2, v3);

                uint32_t a0, a1, a2, a3;
                asm("cvt.rn.f16x2.f32 %0, %1, %2;" : "=r"(a0) : "f"(s0[1]), "f"(s0[0]));
                asm("cvt.rn.f16x2.f32 %0, %1, %2;" : "=r"(a1) : "f"(s0[3]), "f"(s0[2]));
                asm("cvt.rn.f16x2.f32 %0, %1, %2;" : "=r"(a2) : "f"(s1[1]), "f"(s1[0]));
                asm("cvt.rn.f16x2.f32 %0, %1, %2;" : "=r"(a3) : "f"(s1[3]), "f"(s1[2]));
                asm("ex2.approx.f16x2 %0, %1;" : "=r"(a0) : "r"(a0));
                asm("ex2.approx.f16x2 %0, %1;" : "=r"(a1) : "r"(a1));
                asm("ex2.approx.f16x2 %0, %1;" : "=r"(a2) : "r"(a2));
                asm("ex2.approx.f16x2 %0, %1;" : "=r"(a3) : "r"(a3));
                if (tail) {
                    int kb0 = k0 + g * 16 + 2 * (lane & 3);
                    int kb1 = kb0 + 8;
                    uint32_t m0 = (kb0 >= N ? 0u : 0x0000FFFFu) |
                                  (kb0 + 1 >= N ? 0u : 0xFFFF0000u);
                    uint32_t m1 = (kb1 >= N ? 0u : 0x0000FFFFu) |
                                  (kb1 + 1 >= N ? 0u : 0xFFFF0000u);
                    a0 &= m0; a1 &= m0; a2 &= m1; a3 &= m1;
                }
                uint32_t pa[4] = {a0, a1, a2, a3};
                if (g & 1) {
                    mma16816(oaccO[0], pa, v0, v1, oaccO[0]);
                    mma16816(oaccO[1], pa, v2, v3, oaccO[1]);
                    mma16816(laccO,    pa, ONES, ONES, laccO);
                } else {
                    mma16816(oaccE[0], pa, v0, v1, oaccE[0]);
                    mma16816(oaccE[1], pa, v2, v3, oaccE[1]);
                    mma16816(laccE,    pa, ONES, ONES, laccE);
                }
            }
        }
        __syncthreads();   // protects bufs e&3,(e+1)&3 from prefetch at iter e+2
    }

    const float inv0 = 1.0f / (laccE[0] + laccO[0]);
    const float inv1 = 1.0f / (laccE[2] + laccO[2]);
    const int row0 = qt * QTILE + w * 16 + (lane >> 2);
    const int row1 = row0 + 8;
    const int cbase = hi * DH + 2 * (lane & 3);

#pragma unroll
    for (int rr = 0; rr < 2; rr++) {
        int row = rr ? row1 : row0;
        float inv = rr ? inv1 : inv0;
        if (row < N) {
            size_t off = (size_t)(bi * N + row) * D + cbase;
#pragma unroll
            for (int half8 = 0; half8 < 2; half8++) {
                float a0 = (oaccE[half8][2 * rr]     + oaccO[half8][2 * rr])     * inv;
                float a1 = (oaccE[half8][2 * rr + 1] + oaccO[half8][2 * rr + 1]) * inv;
                __half h0 = __float2half_rn(a0), h1 = __float2half_rn(a1);
                __half l0 = __float2half_rn(a0 - __half2float(h0));
                __half l1 = __float2half_rn(a1 - __half2float(h1));
                *(__half2*)(g_Ohi + off + half8 * 8) = __halves2half2(h0, h1);
                *(__half2*)(g_Olo + off + half8 * 8) = __halves2half2(l0, l1);
            }
        }
    }
}

// ---------------------------------------------------------------------------
// Kernel 3: out = O @ W_out + b_out via split-fp16 MMA (exact to ~1e-7).
// CTA = 128 rows x 128 cols, 8 warps, grid 129 (single wave).
// ---------------------------------------------------------------------------
__global__ void __launch_bounds__(256) proj_mma_kernel(const float* __restrict__ bout,
                                                       float* __restrict__ out) {
    extern __shared__ __align__(16) char psm[];
    __half* sAh = (__half*)psm;                          // 128 x XRS
    __half* sAl = (__half*)(psm + 128 * XRS * 2);        // 128 x XRS
    __half* sWh = (__half*)(psm + 256 * XRS * 2);        // 128 x XRS
    __half* sWl = (__half*)(psm + 384 * XRS * 2);        // 128 x XRS
    const int t = threadIdx.x, w = t >> 5, lane = t & 31;
    const int row0 = blockIdx.x * 128;

    const int grp = lane >> 3, r8 = lane & 7;
    const uint32_t frag = (uint32_t)((((grp & 1) * 8 + r8) * XRS + (grp >> 1) * 8) * 2);
    const uint32_t ahb = smem_u32(sAh), alb = smem_u32(sAl);
    const uint32_t whb = smem_u32(sWh), wlb = smem_u32(sWl);

#pragma unroll
    for (int c = t; c < 2048; c += 256) {
        int r = c >> 4, s = c & 15;
        int row = row0 + r; if (row >= ROWS) row = ROWS - 1;
        cp16(ahb + (uint32_t)((r * XRS + s * 8) * 2), g_Ohi + (size_t)row * D + s * 8);
        cp16(alb + (uint32_t)((r * XRS + s * 8) * 2), g_Olo + (size_t)row * D + s * 8);
        cp16(whb + (uint32_t)((r * XRS + s * 8) * 2), g_pwh + (size_t)r * D + s * 8);
        cp16(wlb + (uint32_t)((r * XRS + s * 8) * 2), g_pwl + (size_t)r * D + s * 8);
    }
    asm volatile("cp.async.commit_group;");
    asm volatile("cp.async.wait_group 0;" ::: "memory");
    __syncthreads();

    float acc[16][4];
#pragma unroll
    for (int i = 0; i < 16; i++)
#pragma unroll
        for (int j = 0; j < 4; j++) acc[i][j] = 0.f;

#pragma unroll
    for (int ks = 0; ks < 8; ks++) {
        uint32_t ah[4], al[4];
        ldsm_x4(ahb + (uint32_t)((w * 16 * XRS + ks * 16) * 2) + frag,
                ah[0], ah[1], ah[2], ah[3]);
        ldsm_x4(alb + (uint32_t)((w * 16 * XRS + ks * 16) * 2) + frag,
                al[0], al[1], al[2], al[3]);
#pragma unroll
        for (int g = 0; g < 8; g++) {
            uint32_t b0, b1, b2, b3, c0, c1, c2, c3;
            ldsm_x4_t(whb + (uint32_t)((ks * 16 * XRS + g * 16) * 2) + frag,
                      b0, b1, b2, b3);
            ldsm_x4_t(wlb + (uint32_t)((ks * 16 * XRS + g * 16) * 2) + frag,
                      c0, c1, c2, c3);
            mma16816(acc[2 * g],     ah, b0, b1, acc[2 * g]);
            mma16816(acc[2 * g],     ah, c0, c1, acc[2 * g]);
            mma16816(acc[2 * g],     al, b0, b1, acc[2 * g]);
            mma16816(acc[2 * g + 1], ah, b2, b3, acc[2 * g + 1]);
            mma16816(acc[2 * g + 1], ah, c2, c3, acc[2 * g + 1]);
            mma16816(acc[2 * g + 1], al, b2, b3, acc[2 * g + 1]);
        }
    }

    const int r0 = row0 + w * 16 + (lane >> 2);
#pragma unroll
    for (int nt = 0; nt < 16; nt++) {
        const int c0 = nt * 8 + 2 * (lane & 3);
        const float b0v = bout[c0], b1v = bout[c0 + 1];
#pragma unroll
        for (int rr = 0; rr < 2; rr++) {
            int row = r0 + rr * 8;
            if (row < ROWS) {
                float2 v = make_float2(acc[nt][2 * rr] + b0v, acc[nt][2 * rr + 1] + b1v);
                *(float2*)(out + row * 128 + c0) = v;
            }
        }
    }
}

// ---------------------------------------------------------------------------
extern "C" void kernel_launch(void* const* d_in, const int* in_sizes, int n_in,
                              void* d_out, int out_size) {
    const float* x     = (const float*)d_in[0];
    const float* Wqkv  = (const float*)d_in[1];
    const float* bqkv  = (const float*)d_in[2];
    const float* Wout  = (const float*)d_in[3];
    const float* bout  = (const float*)d_in[4];
    float* out = (float*)d_out;

    cudaFuncSetAttribute(qkv_mma_kernel,
                         cudaFuncAttributeMaxDynamicSharedMemorySize, QKV_SMEM);
    cudaFuncSetAttribute(proj_mma_kernel,
                         cudaFuncAttributeMaxDynamicSharedMemorySize, PROJ_SMEM);

    conv_kernel<<<256, 256>>>(x, Wqkv, Wout);
    qkv_mma_kernel<<<dim3((ROWS + 63) / 64, 3), 128, QKV_SMEM>>>(bqkv);
    attn_kernel<<<dim3(NQT, H, BATCH), 256>>>();
    proj_mma_kernel<<<(ROWS + 127) / 128, 256, PROJ_SMEM>>>(bout, out);
}

// round 15
// speedup vs baseline: 1.0317x; 1.0317x over previous
#include <cuda_runtime.h>
#include <cuda_fp16.h>
#include <cstdint>

#define BATCH 4
#define N 4097
#define D 128
#define H 8
#define DH 16
#define ROWS (BATCH * N)
#define KTILE 128
#define QTILE 128
#define NKT 33
#define NQT 33
#define HALF1 17      // key-tile split point
#define RS 24         // half-stride for 16-col tiles (48B, ldsm conflict-free)
#define XRS 136       // 128-col tile row stride (halfs)

#define QKV_SMEM   ((64 * XRS + 128 * XRS) * 2)     // 52224 B
#define PROJ_SMEM  (4 * 128 * XRS * 2)              // 139264 B

// ---------------- scratch (allocation-free rule) ----------------
__device__ __align__(16) __half g_Q[ROWS * D];
__device__ __align__(16) __half g_K[ROWS * D];
__device__ __align__(16) __half g_V[ROWS * D];
__device__ __align__(16) float  g_Op[2 * ROWS * D];   // split-KV partial O
__device__ __align__(16) float  g_lp[2 * ROWS * H];   // split-KV partial l
__device__ __align__(16) __half g_xh[ROWS * D];       // x in fp16
__device__ __align__(16) __half g_wqh[D * 384];       // W_qkv in fp16
__device__ __align__(16) __half g_pwh[D * D];         // W_out hi
__device__ __align__(16) __half g_pwl[D * D];         // W_out lo

__device__ __forceinline__ uint32_t smem_u32(const void* p) {
    uint32_t a;
    asm("{ .reg .u64 t; cvta.to.shared.u64 t, %1; cvt.u32.u64 %0, t; }" : "=r"(a) : "l"(p));
    return a;
}
__device__ __forceinline__ void ldsm_x4(uint32_t a, uint32_t& r0, uint32_t& r1,
                                        uint32_t& r2, uint32_t& r3) {
    asm volatile("ldmatrix.sync.aligned.m8n8.x4.shared.b16 {%0,%1,%2,%3}, [%4];"
                 : "=r"(r0), "=r"(r1), "=r"(r2), "=r"(r3) : "r"(a));
}
__device__ __forceinline__ void ldsm_x4_t(uint32_t a, uint32_t& r0, uint32_t& r1,
                                          uint32_t& r2, uint32_t& r3) {
    asm volatile("ldmatrix.sync.aligned.m8n8.x4.trans.shared.b16 {%0,%1,%2,%3}, [%4];"
                 : "=r"(r0), "=r"(r1), "=r"(r2), "=r"(r3) : "r"(a));
}
__device__ __forceinline__ void mma16816(float* d, const uint32_t* a,
                                         uint32_t b0, uint32_t b1, const float* c) {
    asm volatile("mma.sync.aligned.m16n8k16.row.col.f32.f16.f16.f32 "
        "{%0,%1,%2,%3}, {%4,%5,%6,%7}, {%8,%9}, {%10,%11,%12,%13};"
        : "=f"(d[0]), "=f"(d[1]), "=f"(d[2]), "=f"(d[3])
        : "r"(a[0]), "r"(a[1]), "r"(a[2]), "r"(a[3]), "r"(b0), "r"(b1),
          "f"(c[0]), "f"(c[1]), "f"(c[2]), "f"(c[3]));
}
__device__ __forceinline__ uint4 cvt4(float4 a, float4 b) {
    uint4 u;
    __half2 h0 = __floats2half2_rn(a.x, a.y), h1 = __floats2half2_rn(a.z, a.w);
    __half2 h2 = __floats2half2_rn(b.x, b.y), h3 = __floats2half2_rn(b.z, b.w);
    u.x = *(uint32_t*)&h0; u.y = *(uint32_t*)&h1;
    u.z = *(uint32_t*)&h2; u.w = *(uint32_t*)&h3;
    return u;
}
__device__ __forceinline__ void cp16(uint32_t dst, const void* src) {
    asm volatile("cp.async.cg.shared.global [%0], [%1], 16;"
                 :: "r"(dst), "l"(src));
}

// ---------------------------------------------------------------------------
// Kernel 0: one-shot conversions
// ---------------------------------------------------------------------------
__global__ void conv_kernel(const float* __restrict__ x,
                            const float* __restrict__ Wqkv,
                            const float* __restrict__ Wout) {
    const int tid = blockIdx.x * blockDim.x + threadIdx.x;
    const int nt = gridDim.x * blockDim.x;

    for (int i = tid; i < (ROWS * D) / 8; i += nt) {
        const float4* s = (const float4*)x + 2 * i;
        ((uint4*)g_xh)[i] = cvt4(s[0], s[1]);
    }
    for (int i = tid; i < (D * 384) / 8; i += nt) {
        const float4* s = (const float4*)Wqkv + 2 * i;
        ((uint4*)g_wqh)[i] = cvt4(s[0], s[1]);
    }
    for (int i = tid; i < (D * D) / 8; i += nt) {
        const float4* s = (const float4*)Wout + 2 * i;
        float4 f0 = s[0], f1 = s[1];
        float wv[8] = {f0.x, f0.y, f0.z, f0.w, f1.x, f1.y, f1.z, f1.w};
        __half hh[8], hl[8];
#pragma unroll
        for (int k = 0; k < 8; k++) {
            hh[k] = __float2half_rn(wv[k]);
            hl[k] = __float2half_rn(wv[k] - __half2float(hh[k]));
        }
        ((uint4*)g_pwh)[i] = *(uint4*)hh;
        ((uint4*)g_pwl)[i] = *(uint4*)hl;
    }
}

// ---------------------------------------------------------------------------
// Kernel 1: QKV GEMM (unchanged R12 best).
// ---------------------------------------------------------------------------
__global__ void __launch_bounds__(128) qkv_mma_kernel(const float* __restrict__ bias) {
    extern __shared__ __align__(16) char qsm[];
    __half* xs = (__half*)qsm;
    __half* ws = (__half*)(qsm + 64 * XRS * 2);
    const int t = threadIdx.x, w = t >> 5, lane = t & 31;
    const int row0 = blockIdx.x * 64;
    const int cg = blockIdx.y * 128;

    const int grp = lane >> 3, r8 = lane & 7;
    const uint32_t fragA = (uint32_t)((((grp & 1) * 8 + r8) * XRS + (grp >> 1) * 8) * 2);
    const uint32_t xsb = smem_u32(xs), wsb = smem_u32(ws);

#pragma unroll
    for (int c = t; c < 1024; c += 128) {
        int r = c >> 4, s = c & 15;
        int row = row0 + r; if (row >= ROWS) row = ROWS - 1;
        cp16(xsb + (uint32_t)((r * XRS + s * 8) * 2), g_xh + (size_t)row * D + s * 8);
    }
#pragma unroll
    for (int c = t; c < 2048; c += 128) {
        int r = c >> 4, s = c & 15;
        cp16(wsb + (uint32_t)((r * XRS + s * 8) * 2), g_wqh + (size_t)r * 384 + cg + s * 8);
    }
    asm volatile("cp.async.commit_group;");
    asm volatile("cp.async.wait_group 0;" ::: "memory");
    __syncthreads();

    float acc[16][4];
#pragma unroll
    for (int i = 0; i < 16; i++)
#pragma unroll
        for (int j = 0; j < 4; j++) acc[i][j] = 0.f;

#pragma unroll
    for (int ks = 0; ks < 8; ks++) {
        uint32_t af[4];
        ldsm_x4(xsb + (uint32_t)((w * 16 * XRS + ks * 16) * 2) + fragA,
                af[0], af[1], af[2], af[3]);
#pragma unroll
        for (int g = 0; g < 8; g++) {
            uint32_t b0, b1, b2, b3;
            ldsm_x4_t(wsb + (uint32_t)((ks * 16 * XRS + g * 16) * 2) + fragA,
                      b0, b1, b2, b3);
            mma16816(acc[2 * g],     af, b0, b1, acc[2 * g]);
            mma16816(acc[2 * g + 1], af, b2, b3, acc[2 * g + 1]);
        }
    }

    const float QSCALE = (float)(0.08838834764831845 * 1.4426950408889634);
    __half* dst = (blockIdx.y == 0) ? g_Q : (blockIdx.y == 1 ? g_K : g_V);
    const float sc = (blockIdx.y == 0) ? QSCALE : 1.0f;
    const int r0 = row0 + w * 16 + (lane >> 2);
#pragma unroll
    for (int nt = 0; nt < 16; nt++) {
        const int col = nt * 8 + 2 * (lane & 3);
        const float b0v = bias[cg + col], b1v = bias[cg + col + 1];
#pragma unroll
        for (int rr = 0; rr < 2; rr++) {
            int row = r0 + rr * 8;
            if (row < ROWS) {
                __half2 hv = __floats2half2_rn((acc[nt][2 * rr]     + b0v) * sc,
                                               (acc[nt][2 * rr + 1] + b1v) * sc);
                *(__half2*)(dst + row * D + col) = hv;
            }
        }
    }
}

// ---------------------------------------------------------------------------
// Kernel 2: FA2 fp16 flash attention, SPLIT-KV (2 halves per q-tile).
// R12 inner loop unchanged; blockIdx.x = qt*2 + kv_half; fp32 partial output.
// ---------------------------------------------------------------------------
__global__ void __launch_bounds__(256, 3) attn_kernel() {
    __shared__ __align__(16) __half sQ[QTILE * RS];
    __shared__ __align__(16) __half sK[2][KTILE * RS];
    __shared__ __align__(16) __half sV[2][KTILE * RS];

    const int t = threadIdx.x, w = t >> 5, lane = t & 31;
    const int qj = blockIdx.x, hi = blockIdx.y, bi = blockIdx.z;
    const int qt = qj >> 1, kh = qj & 1;
    const int kt0 = kh ? HALF1 : 0;
    const int kt1 = kh ? NKT : HALF1;

    const __half* Qb = g_Q + (size_t)(bi * N) * D + hi * DH;
    const __half* Kb = g_K + (size_t)(bi * N) * D + hi * DH;
    const __half* Vb = g_V + (size_t)(bi * N) * D + hi * DH;

    const int srow = t >> 1, sc8 = (t & 1) * 8;
    {
        int qr = qt * QTILE + srow; if (qr >= N) qr = N - 1;
        *(uint4*)(sQ + srow * RS + sc8) = *(const uint4*)(Qb + (size_t)qr * D + sc8);
        int key0 = kt0 * KTILE + srow;   // always < N for first tile of either half
        *(uint4*)(sK[0] + srow * RS + sc8) = *(const uint4*)(Kb + (size_t)key0 * D + sc8);
        *(uint4*)(sV[0] + srow * RS + sc8) = *(const uint4*)(Vb + (size_t)key0 * D + sc8);
    }
    __syncthreads();

    const int grp = lane >> 3, r8 = lane & 7;
    const uint32_t frag_off =
        (uint32_t)((((grp & 1) * 8 + r8) * RS + (grp >> 1) * 8) * 2);

    uint32_t qf[4];
    ldsm_x4(smem_u32(sQ) + (uint32_t)(w * 16 * RS * 2) + frag_off,
            qf[0], qf[1], qf[2], qf[3]);

    const uint32_t kbase0 = smem_u32(sK[0]) + frag_off;
    const uint32_t kbase1 = smem_u32(sK[1]) + frag_off;
    const uint32_t vbase0 = smem_u32(sV[0]) + frag_off;
    const uint32_t vbase1 = smem_u32(sV[1]) + frag_off;
    const uint32_t kdst0 = smem_u32(sK[0] + srow * RS + sc8);
    const uint32_t kdst1 = smem_u32(sK[1] + srow * RS + sc8);
    const uint32_t vdst0 = smem_u32(sV[0] + srow * RS + sc8);
    const uint32_t vdst1 = smem_u32(sV[1] + srow * RS + sc8);
    const uint32_t ONES = 0x3C003C00u;
    const float z4[4] = {0.f, 0.f, 0.f, 0.f};

    float oaccE[2][4] = {{0.f,0.f,0.f,0.f},{0.f,0.f,0.f,0.f}};
    float oaccO[2][4] = {{0.f,0.f,0.f,0.f},{0.f,0.f,0.f,0.f}};
    float laccE[4] = {0.f,0.f,0.f,0.f};
    float laccO[4] = {0.f,0.f,0.f,0.f};

    for (int kt = kt0; kt < kt1; kt++) {
        const int k0 = kt * KTILE;
        const int cur = (kt - kt0) & 1;

        if (kt + 1 < kt1) {
            int key = k0 + KTILE + srow;
            int sz = (key < N) ? 16 : 0;
            int keyc = (key < N) ? key : (N - 1);
            const __half* srcK = Kb + (size_t)keyc * D + sc8;
            const __half* srcV = Vb + (size_t)keyc * D + sc8;
            uint32_t dK = cur ? kdst0 : kdst1;
            uint32_t dV = cur ? vdst0 : vdst1;
            asm volatile("cp.async.cg.shared.global [%0], [%1], 16, %2;"
                         :: "r"(dK), "l"(srcK), "r"(sz));
            asm volatile("cp.async.cg.shared.global [%0], [%1], 16, %2;"
                         :: "r"(dV), "l"(srcV), "r"(sz));
        }
        asm volatile("cp.async.commit_group;");

        const uint32_t kbase = cur ? kbase1 : kbase0;
        const uint32_t vbase = cur ? vbase1 : vbase0;
        const bool tail = (k0 + KTILE > N);

#pragma unroll
        for (int g = 0; g < 8; g++) {
            uint32_t b0, b1, b2, b3;
            ldsm_x4(kbase + (uint32_t)(g * 16 * RS * 2), b0, b1, b2, b3);
            float s0[4], s1[4];
            mma16816(s0, qf, b0, b2, z4);
            mma16816(s1, qf, b1, b3, z4);

            uint32_t v0, v1, v2, v3;
            ldsm_x4_t(vbase + (uint32_t)(g * 16 * RS * 2), v0, v1, v2, v3);

            uint32_t a0, a1, a2, a3;
            asm("cvt.rn.f16x2.f32 %0, %1, %2;" : "=r"(a0) : "f"(s0[1]), "f"(s0[0]));
            asm("cvt.rn.f16x2.f32 %0, %1, %2;" : "=r"(a1) : "f"(s0[3]), "f"(s0[2]));
            asm("cvt.rn.f16x2.f32 %0, %1, %2;" : "=r"(a2) : "f"(s1[1]), "f"(s1[0]));
            asm("cvt.rn.f16x2.f32 %0, %1, %2;" : "=r"(a3) : "f"(s1[3]), "f"(s1[2]));
            asm("ex2.approx.f16x2 %0, %1;" : "=r"(a0) : "r"(a0));
            asm("ex2.approx.f16x2 %0, %1;" : "=r"(a1) : "r"(a1));
            asm("ex2.approx.f16x2 %0, %1;" : "=r"(a2) : "r"(a2));
            asm("ex2.approx.f16x2 %0, %1;" : "=r"(a3) : "r"(a3));
            if (tail) {
                int kb0 = k0 + g * 16 + 2 * (lane & 3);
                int kb1 = kb0 + 8;
                uint32_t m0 = (kb0 >= N ? 0u : 0x0000FFFFu) |
                              (kb0 + 1 >= N ? 0u : 0xFFFF0000u);
                uint32_t m1 = (kb1 >= N ? 0u : 0x0000FFFFu) |
                              (kb1 + 1 >= N ? 0u : 0xFFFF0000u);
                a0 &= m0; a1 &= m0; a2 &= m1; a3 &= m1;
            }
            uint32_t pa[4] = {a0, a1, a2, a3};
            if (g & 1) {
                mma16816(oaccO[0], pa, v0, v1, oaccO[0]);
                mma16816(oaccO[1], pa, v2, v3, oaccO[1]);
                mma16816(laccO,    pa, ONES, ONES, laccO);
            } else {
                mma16816(oaccE[0], pa, v0, v1, oaccE[0]);
                mma16816(oaccE[1], pa, v2, v3, oaccE[1]);
                mma16816(laccE,    pa, ONES, ONES, laccE);
            }
        }

        asm volatile("cp.async.wait_group 0;" ::: "memory");
        __syncthreads();
    }

    // epilogue: write fp32 partial O and l
    float* Op = g_Op + (size_t)kh * ROWS * D;
    float* lp = g_lp + (size_t)kh * ROWS * H;
    const int row0 = qt * QTILE + w * 16 + (lane >> 2);
    const int row1 = row0 + 8;
    const int cbase = hi * DH + 2 * (lane & 3);

#pragma unroll
    for (int rr = 0; rr < 2; rr++) {
        int row = rr ? row1 : row0;
        if (row < N) {
            size_t off = (size_t)(bi * N + row) * D + cbase;
            float2 v0 = make_float2(oaccE[0][2*rr]   + oaccO[0][2*rr],
                                    oaccE[0][2*rr+1] + oaccO[0][2*rr+1]);
            float2 v1 = make_float2(oaccE[1][2*rr]   + oaccO[1][2*rr],
                                    oaccE[1][2*rr+1] + oaccO[1][2*rr+1]);
            *(float2*)(Op + off)     = v0;
            *(float2*)(Op + off + 8) = v1;
            if ((lane & 3) == 0)
                lp[(size_t)(bi * N + row) * H + hi] = laccE[2*rr] + laccO[2*rr];
        }
    }
}

// ---------------------------------------------------------------------------
// Kernel 3: out = O @ W_out + b_out. Split-KV combine fused into A staging:
// A = (P0+P1)/(l0+l1), split hi/lo in smem. 128 rows/CTA, 8 warps.
// ---------------------------------------------------------------------------
__global__ void __launch_bounds__(256) proj_mma_kernel(const float* __restrict__ bout,
                                                       float* __restrict__ out) {
    extern __shared__ __align__(16) char psm[];
    __half* sAh = (__half*)psm;                          // 128 x XRS
    __half* sAl = (__half*)(psm + 128 * XRS * 2);
    __half* sWh = (__half*)(psm + 256 * XRS * 2);
    __half* sWl = (__half*)(psm + 384 * XRS * 2);
    const int t = threadIdx.x, w = t >> 5, lane = t & 31;
    const int row0 = blockIdx.x * 128;

    const int grp = lane >> 3, r8 = lane & 7;
    const uint32_t frag = (uint32_t)((((grp & 1) * 8 + r8) * XRS + (grp >> 1) * 8) * 2);
    const uint32_t ahb = smem_u32(sAh), alb = smem_u32(sAl);
    const uint32_t whb = smem_u32(sWh), wlb = smem_u32(sWl);

    // W hi/lo via cp.async (pre-split)
#pragma unroll
    for (int c = t; c < 2048; c += 256) {
        int r = c >> 4, s = c & 15;
        cp16(whb + (uint32_t)((r * XRS + s * 8) * 2), g_pwh + (size_t)r * D + s * 8);
        cp16(wlb + (uint32_t)((r * XRS + s * 8) * 2), g_pwl + (size_t)r * D + s * 8);
    }
    asm volatile("cp.async.commit_group;");

    // A: combine split-KV partials, normalize, split hi/lo
    const float* P0 = g_Op;
    const float* P1 = g_Op + (size_t)ROWS * D;
#pragma unroll
    for (int c = t; c < 2048; c += 256) {
        int r = c >> 4, s = c & 15;
        int row = row0 + r; if (row >= ROWS) row = ROWS - 1;
        int head = s >> 1;
        float l = g_lp[(size_t)row * H + head] +
                  g_lp[(size_t)ROWS * H + (size_t)row * H + head];
        float inv = 1.0f / l;
        const float4* a0p = (const float4*)(P0 + (size_t)row * D + s * 8);
        const float4* a1p = (const float4*)(P1 + (size_t)row * D + s * 8);
        float4 x0 = a0p[0], x1 = a0p[1], y0 = a1p[0], y1 = a1p[1];
        float v[8] = {(x0.x + y0.x) * inv, (x0.y + y0.y) * inv,
                      (x0.z + y0.z) * inv, (x0.w + y0.w) * inv,
                      (x1.x + y1.x) * inv, (x1.y + y1.y) * inv,
                      (x1.z + y1.z) * inv, (x1.w + y1.w) * inv};
        __half hh[8], hl[8];
#pragma unroll
        for (int k = 0; k < 8; k++) {
            hh[k] = __float2half_rn(v[k]);
            hl[k] = __float2half_rn(v[k] - __half2float(hh[k]));
        }
        *(uint4*)(sAh + r * XRS + s * 8) = *(uint4*)hh;
        *(uint4*)(sAl + r * XRS + s * 8) = *(uint4*)hl;
    }
    asm volatile("cp.async.wait_group 0;" ::: "memory");
    __syncthreads();

    float acc[16][4];
#pragma unroll
    for (int i = 0; i < 16; i++)
#pragma unroll
        for (int j = 0; j < 4; j++) acc[i][j] = 0.f;

#pragma unroll
    for (int ks = 0; ks < 8; ks++) {
        uint32_t ah[4], al[4];
        ldsm_x4(ahb + (uint32_t)((w * 16 * XRS + ks * 16) * 2) + frag,
                ah[0], ah[1], ah[2], ah[3]);
        ldsm_x4(alb + (uint32_t)((w * 16 * XRS + ks * 16) * 2) + frag,
                al[0], al[1], al[2], al[3]);
#pragma unroll
        for (int g = 0; g < 8; g++) {
            uint32_t b0, b1, b2, b3, c0, c1, c2, c3;
            ldsm_x4_t(whb + (uint32_t)((ks * 16 * XRS + g * 16) * 2) + frag,
                      b0, b1, b2, b3);
            ldsm_x4_t(wlb + (uint32_t)((ks * 16 * XRS + g * 16) * 2) + frag,
                      c0, c1, c2, c3);
            mma16816(acc[2 * g],     ah, b0, b1, acc[2 * g]);
            mma16816(acc[2 * g],     ah, c0, c1, acc[2 * g]);
            mma16816(acc[2 * g],     al, b0, b1, acc[2 * g]);
            mma16816(acc[2 * g + 1], ah, b2, b3, acc[2 * g + 1]);
            mma16816(acc[2 * g + 1], ah, c2, c3, acc[2 * g + 1]);
            mma16816(acc[2 * g + 1], al, b2, b3, acc[2 * g + 1]);
        }
    }

    const int r0 = row0 + w * 16 + (lane >> 2);
#pragma unroll
    for (int nt = 0; nt < 16; nt++) {
        const int c0 = nt * 8 + 2 * (lane & 3);
        const float b0v = bout[c0], b1v = bout[c0 + 1];
#pragma unroll
        for (int rr = 0; rr < 2; rr++) {
            int row = r0 + rr * 8;
            if (row < ROWS) {
                float2 v = make_float2(acc[nt][2 * rr] + b0v, acc[nt][2 * rr + 1] + b1v);
                *(float2*)(out + row * 128 + c0) = v;
            }
        }
    }
}

// ---------------------------------------------------------------------------
extern "C" void kernel_launch(void* const* d_in, const int* in_sizes, int n_in,
                              void* d_out, int out_size) {
    const float* x     = (const float*)d_in[0];
    const float* Wqkv  = (const float*)d_in[1];
    const float* bqkv  = (const float*)d_in[2];
    const float* Wout  = (const float*)d_in[3];
    const float* bout  = (const float*)d_in[4];
    float* out = (float*)d_out;

    cudaFuncSetAttribute(qkv_mma_kernel,
                         cudaFuncAttributeMaxDynamicSharedMemorySize, QKV_SMEM);
    cudaFuncSetAttribute(proj_mma_kernel,
                         cudaFuncAttributeMaxDynamicSharedMemorySize, PROJ_SMEM);

    conv_kernel<<<256, 256>>>(x, Wqkv, Wout);
    qkv_mma_kernel<<<dim3((ROWS + 63) / 64, 3), 128, QKV_SMEM>>>(bqkv);
    attn_kernel<<<dim3(NQT * 2, H, BATCH), 256>>>();
    proj_mma_kernel<<<(ROWS + 127) / 128, 256, PROJ_SMEM>>>(bout, out);
}

// round 16
// speedup vs baseline: 1.1538x; 1.1183x over previous
#include <cuda_runtime.h>
#include <cuda_fp16.h>
#include <cstdint>

#define BATCH 4
#define N 4097
#define D 128
#define H 8
#define DH 16
#define ROWS (BATCH * N)
#define KTILE 128
#define QTILE 128
#define NKT 33
#define NQT 33
#define RS 24    // half-stride for 16-col tiles (48B, ldsm conflict-free)
#define XRS 136  // 128-col tile row stride (halfs)

#define QKV_SMEM   ((64 * XRS + 128 * XRS) * 2)     // 52224 B
#define PROJ_SMEM  (4 * 128 * XRS * 2)              // 139264 B

// ---------------- scratch (allocation-free rule) ----------------
// Flat layouts [row][128], column = head*16 + d. Q pre-scaled by d^-.5*log2e.
__device__ __align__(16) __half g_Q[ROWS * D];
__device__ __align__(16) __half g_K[ROWS * D];
__device__ __align__(16) __half g_V[ROWS * D];
__device__ __align__(16) __half g_Ohi[ROWS * D];
__device__ __align__(16) __half g_Olo[ROWS * D];
__device__ __align__(16) __half g_xh[ROWS * D];     // x in fp16
__device__ __align__(16) __half g_wqh[D * 384];     // W_qkv in fp16
__device__ __align__(16) __half g_pwh[D * D];       // W_out hi
__device__ __align__(16) __half g_pwl[D * D];       // W_out lo

__device__ __forceinline__ uint32_t smem_u32(const void* p) {
    uint32_t a;
    asm("{ .reg .u64 t; cvta.to.shared.u64 t, %1; cvt.u32.u64 %0, t; }" : "=r"(a) : "l"(p));
    return a;
}
__device__ __forceinline__ void ldsm_x4(uint32_t a, uint32_t& r0, uint32_t& r1,
                                        uint32_t& r2, uint32_t& r3) {
    asm volatile("ldmatrix.sync.aligned.m8n8.x4.shared.b16 {%0,%1,%2,%3}, [%4];"
                 : "=r"(r0), "=r"(r1), "=r"(r2), "=r"(r3) : "r"(a));
}
__device__ __forceinline__ void ldsm_x4_t(uint32_t a, uint32_t& r0, uint32_t& r1,
                                          uint32_t& r2, uint32_t& r3) {
    asm volatile("ldmatrix.sync.aligned.m8n8.x4.trans.shared.b16 {%0,%1,%2,%3}, [%4];"
                 : "=r"(r0), "=r"(r1), "=r"(r2), "=r"(r3) : "r"(a));
}
__device__ __forceinline__ void mma16816(float* d, const uint32_t* a,
                                         uint32_t b0, uint32_t b1, const float* c) {
    asm volatile("mma.sync.aligned.m16n8k16.row.col.f32.f16.f16.f32 "
        "{%0,%1,%2,%3}, {%4,%5,%6,%7}, {%8,%9}, {%10,%11,%12,%13};"
        : "=f"(d[0]), "=f"(d[1]), "=f"(d[2]), "=f"(d[3])
        : "r"(a[0]), "r"(a[1]), "r"(a[2]), "r"(a[3]), "r"(b0), "r"(b1),
          "f"(c[0]), "f"(c[1]), "f"(c[2]), "f"(c[3]));
}
__device__ __forceinline__ uint4 cvt4(float4 a, float4 b) {
    uint4 u;
    __half2 h0 = __floats2half2_rn(a.x, a.y), h1 = __floats2half2_rn(a.z, a.w);
    __half2 h2 = __floats2half2_rn(b.x, b.y), h3 = __floats2half2_rn(b.z, b.w);
    u.x = *(uint32_t*)&h0; u.y = *(uint32_t*)&h1;
    u.z = *(uint32_t*)&h2; u.w = *(uint32_t*)&h3;
    return u;
}
__device__ __forceinline__ void cp16(uint32_t dst, const void* src) {
    asm volatile("cp.async.cg.shared.global [%0], [%1], 16;"
                 :: "r"(dst), "l"(src));
}

// ---------------------------------------------------------------------------
// Kernel 0: one-shot conversions (x->fp16, W_qkv->fp16, W_out->hi/lo fp16)
// ---------------------------------------------------------------------------
__global__ void conv_kernel(const float* __restrict__ x,
                            const float* __restrict__ Wqkv,
                            const float* __restrict__ Wout) {
    const int tid = blockIdx.x * blockDim.x + threadIdx.x;
    const int nt = gridDim.x * blockDim.x;

    for (int i = tid; i < (ROWS * D) / 8; i += nt) {
        const float4* s = (const float4*)x + 2 * i;
        ((uint4*)g_xh)[i] = cvt4(s[0], s[1]);
    }
    for (int i = tid; i < (D * 384) / 8; i += nt) {
        const float4* s = (const float4*)Wqkv + 2 * i;
        ((uint4*)g_wqh)[i] = cvt4(s[0], s[1]);
    }
    for (int i = tid; i < (D * D) / 8; i += nt) {
        const float4* s = (const float4*)Wout + 2 * i;
        float4 f0 = s[0], f1 = s[1];
        float wv[8] = {f0.x, f0.y, f0.z, f0.w, f1.x, f1.y, f1.z, f1.w};
        __half hh[8], hl[8];
#pragma unroll
        for (int k = 0; k < 8; k++) {
            hh[k] = __float2half_rn(wv[k]);
            hl[k] = __float2half_rn(wv[k] - __half2float(hh[k]));
        }
        ((uint4*)g_pwh)[i] = *(uint4*)hh;
        ((uint4*)g_pwl)[i] = *(uint4*)hl;
    }
}

// ---------------------------------------------------------------------------
// Kernel 1: QKV GEMM. CTA = 64 rows x 128 cols (tensor = blockIdx.y).
// Staging in TWO commit groups: (x + W rows 0-63), (W rows 64-127).
// Compute ks 0-3 after the first group, ks 4-7 after the second.
// ---------------------------------------------------------------------------
__global__ void __launch_bounds__(128) qkv_mma_kernel(const float* __restrict__ bias) {
    extern __shared__ __align__(16) char qsm[];
    __half* xs = (__half*)qsm;                       // 64 x XRS
    __half* ws = (__half*)(qsm + 64 * XRS * 2);      // 128 x XRS
    const int t = threadIdx.x, w = t >> 5, lane = t & 31;
    const int row0 = blockIdx.x * 64;
    const int cg = blockIdx.y * 128;

    const int grp = lane >> 3, r8 = lane & 7;
    const uint32_t fragA = (uint32_t)((((grp & 1) * 8 + r8) * XRS + (grp >> 1) * 8) * 2);
    const uint32_t xsb = smem_u32(xs), wsb = smem_u32(ws);

    // group 1: x tile + W rows 0-63
#pragma unroll
    for (int c = t; c < 1024; c += 128) {
        int r = c >> 4, s = c & 15;
        int row = row0 + r; if (row >= ROWS) row = ROWS - 1;
        cp16(xsb + (uint32_t)((r * XRS + s * 8) * 2), g_xh + (size_t)row * D + s * 8);
    }
#pragma unroll
    for (int c = t; c < 1024; c += 128) {
        int r = c >> 4, s = c & 15;
        cp16(wsb + (uint32_t)((r * XRS + s * 8) * 2), g_wqh + (size_t)r * 384 + cg + s * 8);
    }
    asm volatile("cp.async.commit_group;");
    // group 2: W rows 64-127
#pragma unroll
    for (int c = t; c < 1024; c += 128) {
        int r = (c >> 4) + 64, s = c & 15;
        cp16(wsb + (uint32_t)((r * XRS + s * 8) * 2), g_wqh + (size_t)r * 384 + cg + s * 8);
    }
    asm volatile("cp.async.commit_group;");

    float acc[16][4];
#pragma unroll
    for (int i = 0; i < 16; i++)
#pragma unroll
        for (int j = 0; j < 4; j++) acc[i][j] = 0.f;

    asm volatile("cp.async.wait_group 1;" ::: "memory");
    __syncthreads();

#pragma unroll
    for (int ks = 0; ks < 4; ks++) {
        uint32_t af[4];
        ldsm_x4(xsb + (uint32_t)((w * 16 * XRS + ks * 16) * 2) + fragA,
                af[0], af[1], af[2], af[3]);
#pragma unroll
        for (int g = 0; g < 8; g++) {
            uint32_t b0, b1, b2, b3;
            ldsm_x4_t(wsb + (uint32_t)((ks * 16 * XRS + g * 16) * 2) + fragA,
                      b0, b1, b2, b3);
            mma16816(acc[2 * g],     af, b0, b1, acc[2 * g]);
            mma16816(acc[2 * g + 1], af, b2, b3, acc[2 * g + 1]);
        }
    }

    asm volatile("cp.async.wait_group 0;" ::: "memory");
    __syncthreads();

#pragma unroll
    for (int ks = 4; ks < 8; ks++) {
        uint32_t af[4];
        ldsm_x4(xsb + (uint32_t)((w * 16 * XRS + ks * 16) * 2) + fragA,
                af[0], af[1], af[2], af[3]);
#pragma unroll
        for (int g = 0; g < 8; g++) {
            uint32_t b0, b1, b2, b3;
            ldsm_x4_t(wsb + (uint32_t)((ks * 16 * XRS + g * 16) * 2) + fragA,
                      b0, b1, b2, b3);
            mma16816(acc[2 * g],     af, b0, b1, acc[2 * g]);
            mma16816(acc[2 * g + 1], af, b2, b3, acc[2 * g + 1]);
        }
    }

    const float QSCALE = (float)(0.08838834764831845 * 1.4426950408889634);
    __half* dst = (blockIdx.y == 0) ? g_Q : (blockIdx.y == 1 ? g_K : g_V);
    const float sc = (blockIdx.y == 0) ? QSCALE : 1.0f;
    const int r0 = row0 + w * 16 + (lane >> 2);
#pragma unroll
    for (int nt = 0; nt < 16; nt++) {
        const int col = nt * 8 + 2 * (lane & 3);
        const float b0v = bias[cg + col], b1v = bias[cg + col + 1];
#pragma unroll
        for (int rr = 0; rr < 2; rr++) {
            int row = r0 + rr * 8;
            if (row < ROWS) {
                __half2 hv = __floats2half2_rn((acc[nt][2 * rr]     + b0v) * sc,
                                               (acc[nt][2 * rr + 1] + b1v) * sc);
                *(__half2*)(dst + row * D + col) = hv;
            }
        }
    }
}

// ---------------------------------------------------------------------------
// Kernel 2: FA2-style fp16 flash attention (exact R12 champion body).
// QTILE=128, 8 warps, 3 CTAs/SM, double-buffered cp.async, fused QK->exp->PV,
// E/O split accumulators, hi/lo fp16 output.
// ---------------------------------------------------------------------------
__global__ void __launch_bounds__(256, 3) attn_kernel() {
    __shared__ __align__(16) __half sQ[QTILE * RS];
    __shared__ __align__(16) __half sK[2][KTILE * RS];
    __shared__ __align__(16) __half sV[2][KTILE * RS];

    const int t = threadIdx.x, w = t >> 5, lane = t & 31;
    const int qt = blockIdx.x, hi = blockIdx.y, bi = blockIdx.z;

    const __half* Qb = g_Q + (size_t)(bi * N) * D + hi * DH;
    const __half* Kb = g_K + (size_t)(bi * N) * D + hi * DH;
    const __half* Vb = g_V + (size_t)(bi * N) * D + hi * DH;

    const int srow = t >> 1, sc8 = (t & 1) * 8;
    {
        int qr = qt * QTILE + srow; if (qr >= N) qr = N - 1;
        *(uint4*)(sQ + srow * RS + sc8) = *(const uint4*)(Qb + (size_t)qr * D + sc8);
        *(uint4*)(sK[0] + srow * RS + sc8) = *(const uint4*)(Kb + (size_t)srow * D + sc8);
        *(uint4*)(sV[0] + srow * RS + sc8) = *(const uint4*)(Vb + (size_t)srow * D + sc8);
    }
    __syncthreads();

    const int grp = lane >> 3, r8 = lane & 7;
    const uint32_t frag_off =
        (uint32_t)((((grp & 1) * 8 + r8) * RS + (grp >> 1) * 8) * 2);

    uint32_t qf[4];
    ldsm_x4(smem_u32(sQ) + (uint32_t)(w * 16 * RS * 2) + frag_off,
            qf[0], qf[1], qf[2], qf[3]);

    const uint32_t kbase0 = smem_u32(sK[0]) + frag_off;
    const uint32_t kbase1 = smem_u32(sK[1]) + frag_off;
    const uint32_t vbase0 = smem_u32(sV[0]) + frag_off;
    const uint32_t vbase1 = smem_u32(sV[1]) + frag_off;
    const uint32_t kdst0 = smem_u32(sK[0] + srow * RS + sc8);
    const uint32_t kdst1 = smem_u32(sK[1] + srow * RS + sc8);
    const uint32_t vdst0 = smem_u32(sV[0] + srow * RS + sc8);
    const uint32_t vdst1 = smem_u32(sV[1] + srow * RS + sc8);
    const uint32_t ONES = 0x3C003C00u;
    const float z4[4] = {0.f, 0.f, 0.f, 0.f};

    float oaccE[2][4] = {{0.f,0.f,0.f,0.f},{0.f,0.f,0.f,0.f}};
    float oaccO[2][4] = {{0.f,0.f,0.f,0.f},{0.f,0.f,0.f,0.f}};
    float laccE[4] = {0.f,0.f,0.f,0.f};
    float laccO[4] = {0.f,0.f,0.f,0.f};

    for (int kt = 0; kt < NKT; kt++) {
        const int k0 = kt * KTILE;
        const int cur = kt & 1;

        if (kt + 1 < NKT) {
            int key = k0 + KTILE + srow;
            int sz = (key < N) ? 16 : 0;
            int keyc = (key < N) ? key : (N - 1);
            const __half* srcK = Kb + (size_t)keyc * D + sc8;
            const __half* srcV = Vb + (size_t)keyc * D + sc8;
            uint32_t dK = cur ? kdst0 : kdst1;
            uint32_t dV = cur ? vdst0 : vdst1;
            asm volatile("cp.async.cg.shared.global [%0], [%1], 16, %2;"
                         :: "r"(dK), "l"(srcK), "r"(sz));
            asm volatile("cp.async.cg.shared.global [%0], [%1], 16, %2;"
                         :: "r"(dV), "l"(srcV), "r"(sz));
        }
        asm volatile("cp.async.commit_group;");

        const uint32_t kbase = cur ? kbase1 : kbase0;
        const uint32_t vbase = cur ? vbase1 : vbase0;
        const bool tail = (k0 + KTILE > N);

#pragma unroll
        for (int g = 0; g < 8; g++) {
            uint32_t b0, b1, b2, b3;
            ldsm_x4(kbase + (uint32_t)(g * 16 * RS * 2), b0, b1, b2, b3);
            float s0[4], s1[4];
            mma16816(s0, qf, b0, b2, z4);
            mma16816(s1, qf, b1, b3, z4);

            uint32_t v0, v1, v2, v3;
            ldsm_x4_t(vbase + (uint32_t)(g * 16 * RS * 2), v0, v1, v2, v3);

            uint32_t a0, a1, a2, a3;
            asm("cvt.rn.f16x2.f32 %0, %1, %2;" : "=r"(a0) : "f"(s0[1]), "f"(s0[0]));
            asm("cvt.rn.f16x2.f32 %0, %1, %2;" : "=r"(a1) : "f"(s0[3]), "f"(s0[2]));
            asm("cvt.rn.f16x2.f32 %0, %1, %2;" : "=r"(a2) : "f"(s1[1]), "f"(s1[0]));
            asm("cvt.rn.f16x2.f32 %0, %1, %2;" : "=r"(a3) : "f"(s1[3]), "f"(s1[2]));
            asm("ex2.approx.f16x2 %0, %1;" : "=r"(a0) : "r"(a0));
            asm("ex2.approx.f16x2 %0, %1;" : "=r"(a1) : "r"(a1));
            asm("ex2.approx.f16x2 %0, %1;" : "=r"(a2) : "r"(a2));
            asm("ex2.approx.f16x2 %0, %1;" : "=r"(a3) : "r"(a3));
            if (tail) {
                int kb0 = k0 + g * 16 + 2 * (lane & 3);
                int kb1 = kb0 + 8;
                uint32_t m0 = (kb0 >= N ? 0u : 0x0000FFFFu) |
                              (kb0 + 1 >= N ? 0u : 0xFFFF0000u);
                uint32_t m1 = (kb1 >= N ? 0u : 0x0000FFFFu) |
                              (kb1 + 1 >= N ? 0u : 0xFFFF0000u);
                a0 &= m0; a1 &= m0; a2 &= m1; a3 &= m1;
            }
            uint32_t pa[4] = {a0, a1, a2, a3};
            if (g & 1) {
                mma16816(oaccO[0], pa, v0, v1, oaccO[0]);
                mma16816(oaccO[1], pa, v2, v3, oaccO[1]);
                mma16816(laccO,    pa, ONES, ONES, laccO);
            } else {
                mma16816(oaccE[0], pa, v0, v1, oaccE[0]);
                mma16816(oaccE[1], pa, v2, v3, oaccE[1]);
                mma16816(laccE,    pa, ONES, ONES, laccE);
            }
        }

        asm volatile("cp.async.wait_group 0;" ::: "memory");
        __syncthreads();
    }

    const float inv0 = 1.0f / (laccE[0] + laccO[0]);
    const float inv1 = 1.0f / (laccE[2] + laccO[2]);
    const int row0 = qt * QTILE + w * 16 + (lane >> 2);
    const int row1 = row0 + 8;
    const int cbase = hi * DH + 2 * (lane & 3);

#pragma unroll
    for (int rr = 0; rr < 2; rr++) {
        int row = rr ? row1 : row0;
        float inv = rr ? inv1 : inv0;
        if (row < N) {
            size_t off = (size_t)(bi * N + row) * D + cbase;
#pragma unroll
            for (int half8 = 0; half8 < 2; half8++) {
                float a0 = (oaccE[half8][2 * rr]     + oaccO[half8][2 * rr])     * inv;
                float a1 = (oaccE[half8][2 * rr + 1] + oaccO[half8][2 * rr + 1]) * inv;
                __half h0 = __float2half_rn(a0), h1 = __float2half_rn(a1);
                __half l0 = __float2half_rn(a0 - __half2float(h0));
                __half l1 = __float2half_rn(a1 - __half2float(h1));
                *(__half2*)(g_Ohi + off + half8 * 8) = __halves2half2(h0, h1);
                *(__half2*)(g_Olo + off + half8 * 8) = __halves2half2(l0, l1);
            }
        }
    }
}

// ---------------------------------------------------------------------------
// Kernel 3: out = O @ W_out + b_out via split-fp16 MMA (exact to ~1e-7).
// CTA = 128 rows x 128 cols, 8 warps, grid 129 (R14 measured version).
// ---------------------------------------------------------------------------
__global__ void __launch_bounds__(256) proj_mma_kernel(const float* __restrict__ bout,
                                                       float* __restrict__ out) {
    extern __shared__ __align__(16) char psm[];
    __half* sAh = (__half*)psm;                          // 128 x XRS
    __half* sAl = (__half*)(psm + 128 * XRS * 2);
    __half* sWh = (__half*)(psm + 256 * XRS * 2);
    __half* sWl = (__half*)(psm + 384 * XRS * 2);
    const int t = threadIdx.x, w = t >> 5, lane = t & 31;
    const int row0 = blockIdx.x * 128;

    const int grp = lane >> 3, r8 = lane & 7;
    const uint32_t frag = (uint32_t)((((grp & 1) * 8 + r8) * XRS + (grp >> 1) * 8) * 2);
    const uint32_t ahb = smem_u32(sAh), alb = smem_u32(sAl);
    const uint32_t whb = smem_u32(sWh), wlb = smem_u32(sWl);

#pragma unroll
    for (int c = t; c < 2048; c += 256) {
        int r = c >> 4, s = c & 15;
        int row = row0 + r; if (row >= ROWS) row = ROWS - 1;
        cp16(ahb + (uint32_t)((r * XRS + s * 8) * 2), g_Ohi + (size_t)row * D + s * 8);
        cp16(alb + (uint32_t)((r * XRS + s * 8) * 2), g_Olo + (size_t)row * D + s * 8);
        cp16(whb + (uint32_t)((r * XRS + s * 8) * 2), g_pwh + (size_t)r * D + s * 8);
        cp16(wlb + (uint32_t)((r * XRS + s * 8) * 2), g_pwl + (size_t)r * D + s * 8);
    }
    asm volatile("cp.async.commit_group;");
    asm volatile("cp.async.wait_group 0;" ::: "memory");
    __syncthreads();

    float acc[16][4];
#pragma unroll
    for (int i = 0; i < 16; i++)
#pragma unroll
        for (int j = 0; j < 4; j++) acc[i][j] = 0.f;

#pragma unroll
    for (int ks = 0; ks < 8; ks++) {
        uint32_t ah[4], al[4];
        ldsm_x4(ahb + (uint32_t)((w * 16 * XRS + ks * 16) * 2) + frag,
                ah[0], ah[1], ah[2], ah[3]);
        ldsm_x4(alb + (uint32_t)((w * 16 * XRS + ks * 16) * 2) + frag,
                al[0], al[1], al[2], al[3]);
#pragma unroll
        for (int g = 0; g < 8; g++) {
            uint32_t b0, b1, b2, b3, c0, c1, c2, c3;
            ldsm_x4_t(whb + (uint32_t)((ks * 16 * XRS + g * 16) * 2) + frag,
                      b0, b1, b2, b3);
            ldsm_x4_t(wlb + (uint32_t)((ks * 16 * XRS + g * 16) * 2) + frag,
                      c0, c1, c2, c3);
            mma16816(acc[2 * g],     ah, b0, b1, acc[2 * g]);
            mma16816(acc[2 * g],     ah, c0, c1, acc[2 * g]);
            mma16816(acc[2 * g],     al, b0, b1, acc[2 * g]);
            mma16816(acc[2 * g + 1], ah, b2, b3, acc[2 * g + 1]);
            mma16816(acc[2 * g + 1], ah, c2, c3, acc[2 * g + 1]);
            mma16816(acc[2 * g + 1], al, b2, b3, acc[2 * g + 1]);
        }
    }

    const int r0 = row0 + w * 16 + (lane >> 2);
#pragma unroll
    for (int nt = 0; nt < 16; nt++) {
        const int c0 = nt * 8 + 2 * (lane & 3);
        const float b0v = bout[c0], b1v = bout[c0 + 1];
#pragma unroll
        for (int rr = 0; rr < 2; rr++) {
            int row = r0 + rr * 8;
            if (row < ROWS) {
                float2 v = make_float2(acc[nt][2 * rr] + b0v, acc[nt][2 * rr + 1] + b1v);
                *(float2*)(out + row * 128 + c0) = v;
            }
        }
    }
}

// ---------------------------------------------------------------------------
extern "C" void kernel_launch(void* const* d_in, const int* in_sizes, int n_in,
                              void* d_out, int out_size) {
    const float* x     = (const float*)d_in[0];
    const float* Wqkv  = (const float*)d_in[1];
    const float* bqkv  = (const float*)d_in[2];
    const float* Wout  = (const float*)d_in[3];
    const float* bout  = (const float*)d_in[4];
    float* out = (float*)d_out;

    cudaFuncSetAttribute(qkv_mma_kernel,
                         cudaFuncAttributeMaxDynamicSharedMemorySize, QKV_SMEM);
    cudaFuncSetAttribute(proj_mma_kernel,
                         cudaFuncAttributeMaxDynamicSharedMemorySize, PROJ_SMEM);

    conv_kernel<<<256, 256>>>(x, Wqkv, Wout);
    qkv_mma_kernel<<<dim3((ROWS + 63) / 64, 3), 128, QKV_SMEM>>>(bqkv);
    attn_kernel<<<dim3(NQT, H, BATCH), 256>>>();
    proj_mma_kernel<<<(ROWS + 127) / 128, 256, PROJ_SMEM>>>(bout, out);
}